// round 2
// baseline (speedup 1.0000x reference)
#include <cuda_runtime.h>
#include <math.h>

// Problem constants
#define BB   4
#define TTT  4096
#define CC   1024
#define HH   16
#define KD   64          // head dim
#define TCH  128         // chunk length
#define NCH  32          // chunks
#define MM   (BB*TTT)    // 16384 rows

// ---------------- scratch (device globals; no allocation allowed) ----------
__device__ float g_xr[MM*CC];
__device__ float g_xk[MM*CC];
__device__ float g_xv[MM*CC];
__device__ float g_xg[MM*CC];
__device__ float g_r [MM*CC];
__device__ float g_k [MM*CC];
__device__ float g_v [MM*CC];
__device__ float g_g [MM*CC];
__device__ float g_xo[MM*CC];
__device__ float g_z [MM*CC];
__device__ float g_states[BB*HH*NCH*KD*KD];

// ---------------- 1) time-shift mixing ------------------------------------
__global__ void mix_kernel(const float* __restrict__ x,
                           const float* __restrict__ tmk,
                           const float* __restrict__ tmv,
                           const float* __restrict__ tmr,
                           const float* __restrict__ tmg) {
    int idx = blockIdx.x * blockDim.x + threadIdx.x;   // MM*CC total
    int c = idx & (CC - 1);
    int t = (idx >> 10) & (TTT - 1);
    float xc = x[idx];
    float xp = t ? x[idx - CC] : 0.f;
    float mr = tmr[c]; g_xr[idx] = xc * mr + xp * (1.f - mr);
    float mk = tmk[c]; g_xk[idx] = xc * mk + xp * (1.f - mk);
    float mv = tmv[c]; g_xv[idx] = xc * mv + xp * (1.f - mv);
    float mg = tmg[c]; g_xg[idx] = xc * mg + xp * (1.f - mg);
}

// ---------------- 2) GEMM:  C[m,n] = sum_k A[m,k] * W[n,k] -----------------
// A: M x K row-major, W: N x K row-major (i.e. computes A @ W^T)
// Block tile 128x128, BK=16, thread tile 8x8, 256 threads.
__global__ void __launch_bounds__(256)
gemm_xwT(const float* __restrict__ A, const float* __restrict__ W,
         float* __restrict__ Co, int Mtot, int Ntot, int Ktot) {
    __shared__ float As[16][128];
    __shared__ float Bs[16][128];
    int tid = threadIdx.x;
    int tx = tid & 15;       // n sub-tile
    int ty = tid >> 4;       // m sub-tile
    const float* Ab = A + (size_t)blockIdx.y * 128 * Ktot;
    const float* Wb = W + (size_t)blockIdx.x * 128 * Ktot;
    int lrow = tid >> 2;         // 0..63
    int lcol = (tid & 3) * 4;    // 0,4,8,12
    float acc[8][8];
#pragma unroll
    for (int i = 0; i < 8; i++)
#pragma unroll
        for (int j = 0; j < 8; j++) acc[i][j] = 0.f;

    for (int k0 = 0; k0 < Ktot; k0 += 16) {
        float4 a0 = *(const float4*)(Ab + (size_t)lrow        * Ktot + k0 + lcol);
        float4 a1 = *(const float4*)(Ab + (size_t)(lrow + 64) * Ktot + k0 + lcol);
        float4 b0 = *(const float4*)(Wb + (size_t)lrow        * Ktot + k0 + lcol);
        float4 b1 = *(const float4*)(Wb + (size_t)(lrow + 64) * Ktot + k0 + lcol);
        __syncthreads();
        As[lcol + 0][lrow]      = a0.x; As[lcol + 1][lrow]      = a0.y;
        As[lcol + 2][lrow]      = a0.z; As[lcol + 3][lrow]      = a0.w;
        As[lcol + 0][lrow + 64] = a1.x; As[lcol + 1][lrow + 64] = a1.y;
        As[lcol + 2][lrow + 64] = a1.z; As[lcol + 3][lrow + 64] = a1.w;
        Bs[lcol + 0][lrow]      = b0.x; Bs[lcol + 1][lrow]      = b0.y;
        Bs[lcol + 2][lrow]      = b0.z; Bs[lcol + 3][lrow]      = b0.w;
        Bs[lcol + 0][lrow + 64] = b1.x; Bs[lcol + 1][lrow + 64] = b1.y;
        Bs[lcol + 2][lrow + 64] = b1.z; Bs[lcol + 3][lrow + 64] = b1.w;
        __syncthreads();
#pragma unroll
        for (int kk = 0; kk < 16; kk++) {
            float4 ra0 = *(const float4*)&As[kk][ty * 8];
            float4 ra1 = *(const float4*)&As[kk][ty * 8 + 4];
            float4 rb0 = *(const float4*)&Bs[kk][tx * 8];
            float4 rb1 = *(const float4*)&Bs[kk][tx * 8 + 4];
            float am[8] = {ra0.x, ra0.y, ra0.z, ra0.w, ra1.x, ra1.y, ra1.z, ra1.w};
            float bn[8] = {rb0.x, rb0.y, rb0.z, rb0.w, rb1.x, rb1.y, rb1.z, rb1.w};
#pragma unroll
            for (int i = 0; i < 8; i++)
#pragma unroll
                for (int j = 0; j < 8; j++)
                    acc[i][j] = fmaf(am[i], bn[j], acc[i][j]);
        }
    }
    int rowB = blockIdx.y * 128 + ty * 8;
    int colB = blockIdx.x * 128 + tx * 8;
#pragma unroll
    for (int i = 0; i < 8; i++) {
        float4 o0 = make_float4(acc[i][0], acc[i][1], acc[i][2], acc[i][3]);
        float4 o1 = make_float4(acc[i][4], acc[i][5], acc[i][6], acc[i][7]);
        *(float4*)&Co[(size_t)(rowB + i) * Ntot + colB]     = o0;
        *(float4*)&Co[(size_t)(rowB + i) * Ntot + colB + 4] = o1;
    }
}

// ---------------- 3) chunk-boundary states (sequential recurrence) ---------
// grid: (B*H, 4 v-slices), 256 threads. Each block owns s[64, 16] columns.
__global__ void __launch_bounds__(256)
state_kernel(const float* __restrict__ tdecay) {
    __shared__ float kw[TCH * KD];     // k * wk, 32KB
    __shared__ float vsh[TCH * 16];    // v slice, 8KB
    __shared__ float dp[TCH + 1];
    int bh = blockIdx.x;
    int vs = blockIdx.y;
    int b = bh >> 4, h = bh & 15;
    int tid = threadIdx.x;
    float decay = expf(-expf(tdecay[h]));
    if (tid <= TCH) dp[tid] = powf(decay, (float)tid);
    __syncthreads();
    float ws = dp[TCH];                 // decay^128
    int tr = tid >> 2;                  // k-row 0..63
    int tc = (tid & 3) * 4;             // v-col within slice
    float s0 = 0.f, s1 = 0.f, s2 = 0.f, s3 = 0.f;
    const float* kb = g_k + ((size_t)b * TTT) * CC + h * KD;
    const float* vb = g_v + ((size_t)b * TTT) * CC + h * KD + vs * 16;
    float* stb = g_states + ((size_t)bh * NCH) * KD * KD;
    for (int n = 0; n < NCH; n++) {
        float* sd = stb + (size_t)n * KD * KD + tr * KD + vs * 16 + tc;
        sd[0] = s0; sd[1] = s1; sd[2] = s2; sd[3] = s3;   // state at chunk START
        __syncthreads();
        for (int e = tid; e < TCH * KD; e += 256) {
            int j = e >> 6, kk2 = e & 63;
            kw[e] = kb[(size_t)(n * TCH + j) * CC + kk2] * dp[127 - j];
        }
        for (int e = tid; e < TCH * 16; e += 256) {
            int j = e >> 4, cc2 = e & 15;
            vsh[e] = vb[(size_t)(n * TCH + j) * CC + cc2];
        }
        __syncthreads();
        float a0 = 0.f, a1 = 0.f, a2 = 0.f, a3 = 0.f;
#pragma unroll 4
        for (int j = 0; j < TCH; j++) {
            float kv = kw[j * KD + tr];
            float4 v4 = *(const float4*)&vsh[j * 16 + tc];
            a0 = fmaf(kv, v4.x, a0); a1 = fmaf(kv, v4.y, a1);
            a2 = fmaf(kv, v4.z, a2); a3 = fmaf(kv, v4.w, a3);
        }
        s0 = ws * s0 + a0; s1 = ws * s1 + a1;
        s2 = ws * s2 + a2; s3 = ws * s3 + a3;
    }
}

// ---------------- 4) per-chunk attention output (parallel) -----------------
// grid: B*H*N = 2048 blocks, 256 threads, ~182KB dynamic smem.
#define OUT_SMEM_FLOATS (TCH*65 + TCH*65 + TCH*KD + KD*KD + TCH*129)
__global__ void __launch_bounds__(256)
out_kernel(const float* __restrict__ tdecay, const float* __restrict__ tfa) {
    extern __shared__ float sm[];
    float* rs  = sm;                       // 128x65 (padded)
    float* ksm = rs  + TCH * 65;           // 128x65 (padded)
    float* vsm = ksm + TCH * 65;           // 128x64
    float* ssm = vsm + TCH * KD;           // 64x64
    float* att = ssm + KD * KD;            // 128x129 (padded)
    __shared__ float dp[TCH];
    int bhn = blockIdx.x;
    int n  = bhn & (NCH - 1);
    int bh = bhn >> 5;
    int h = bh & 15, b = bh >> 4;
    int tid = threadIdx.x;
    float decay = expf(-expf(tdecay[h]));
    if (tid < TCH) dp[tid] = powf(decay, (float)tid);
    float u = tfa[h];
    size_t base = ((size_t)(b * TTT + n * TCH)) * CC + h * KD;
    for (int e = tid; e < TCH * KD; e += 256) {
        int i = e >> 6, k2 = e & 63;
        size_t gi = base + (size_t)i * CC + k2;
        rs [i * 65 + k2] = g_r[gi];
        ksm[i * 65 + k2] = g_k[gi];
        vsm[e]           = g_v[gi];
    }
    const float* stp = g_states + ((size_t)bh * NCH + n) * KD * KD;
    for (int e = tid; e < KD * KD; e += 256) ssm[e] = stp[e];
    __syncthreads();

    // Phase A: att[i,j] = (r_i . k_j) * w_mat[i,j]; 8x8 tile per thread
    {
        int i0 = (tid >> 4) * 8, j0 = (tid & 15) * 8;
        float acc[8][8];
#pragma unroll
        for (int i = 0; i < 8; i++)
#pragma unroll
            for (int j = 0; j < 8; j++) acc[i][j] = 0.f;
        for (int k2 = 0; k2 < KD; k2++) {
            float ra[8], rb[8];
#pragma unroll
            for (int ii = 0; ii < 8; ii++) ra[ii] = rs[(i0 + ii) * 65 + k2];
#pragma unroll
            for (int jj = 0; jj < 8; jj++) rb[jj] = ksm[(j0 + jj) * 65 + k2];
#pragma unroll
            for (int ii = 0; ii < 8; ii++)
#pragma unroll
                for (int jj = 0; jj < 8; jj++)
                    acc[ii][jj] = fmaf(ra[ii], rb[jj], acc[ii][jj]);
        }
#pragma unroll
        for (int ii = 0; ii < 8; ii++)
#pragma unroll
            for (int jj = 0; jj < 8; jj++) {
                int i = i0 + ii, j = j0 + jj, d = i - j;
                float w = (d > 0) ? dp[d - 1] : ((d == 0) ? u : 0.f);
                att[i * 129 + j] = acc[ii][jj] * w;
            }
    }
    __syncthreads();

    // Phase B: out = att @ v + (r @ s) * decay^i ; 4x8 tile per thread
    {
        int i0 = (tid >> 3) * 4, v0 = (tid & 7) * 8;
        float aA[4][8], aB[4][8];
#pragma unroll
        for (int i = 0; i < 4; i++)
#pragma unroll
            for (int j = 0; j < 8; j++) { aA[i][j] = 0.f; aB[i][j] = 0.f; }
        for (int j = 0; j < TCH; j++) {
            float a4[4];
#pragma unroll
            for (int ii = 0; ii < 4; ii++) a4[ii] = att[(i0 + ii) * 129 + j];
            float4 va = *(const float4*)&vsm[j * KD + v0];
            float4 vb2 = *(const float4*)&vsm[j * KD + v0 + 4];
            float vv[8] = {va.x, va.y, va.z, va.w, vb2.x, vb2.y, vb2.z, vb2.w};
#pragma unroll
            for (int ii = 0; ii < 4; ii++)
#pragma unroll
                for (int jj = 0; jj < 8; jj++)
                    aA[ii][jj] = fmaf(a4[ii], vv[jj], aA[ii][jj]);
        }
        for (int k2 = 0; k2 < KD; k2++) {
            float r4[4];
#pragma unroll
            for (int ii = 0; ii < 4; ii++) r4[ii] = rs[(i0 + ii) * 65 + k2];
            float4 sa = *(const float4*)&ssm[k2 * KD + v0];
            float4 sb = *(const float4*)&ssm[k2 * KD + v0 + 4];
            float sv[8] = {sa.x, sa.y, sa.z, sa.w, sb.x, sb.y, sb.z, sb.w};
#pragma unroll
            for (int ii = 0; ii < 4; ii++)
#pragma unroll
                for (int jj = 0; jj < 8; jj++)
                    aB[ii][jj] = fmaf(r4[ii], sv[jj], aB[ii][jj]);
        }
#pragma unroll
        for (int ii = 0; ii < 4; ii++) {
            float wbv = dp[i0 + ii];
#pragma unroll
            for (int jj = 0; jj < 8; jj++)
                g_xo[base + (size_t)(i0 + ii) * CC + v0 + jj] =
                    aA[ii][jj] + wbv * aB[ii][jj];
        }
    }
}

// ---------------- 5) GroupNorm(/8) + silu gate -----------------------------
__global__ void gn_gate_kernel(const float* __restrict__ lnw,
                               const float* __restrict__ lnb) {
    int gidx = blockIdx.x * blockDim.x + threadIdx.x;
    int warp = gidx >> 5, lane = gidx & 31;
    size_t basep = (size_t)warp * 64;
    float a  = g_xo[basep + lane]      * 0.125f;
    float c2 = g_xo[basep + 32 + lane] * 0.125f;
    float s = a + c2, sq = a * a + c2 * c2;
#pragma unroll
    for (int o = 16; o; o >>= 1) {
        s  += __shfl_xor_sync(0xffffffffu, s,  o);
        sq += __shfl_xor_sync(0xffffffffu, sq, o);
    }
    float mu  = s * (1.f / 64.f);
    float var = sq * (1.f / 64.f) - mu * mu;
    float inv = rsqrtf(var + 1e-5f);
    int h = warp & 15;
    int cb = h * 64;
    float g0r = g_g[basep + lane];
    float g1r = g_g[basep + 32 + lane];
    float y0 = ((a  - mu) * inv) * lnw[cb + lane]      + lnb[cb + lane];
    float y1 = ((c2 - mu) * inv) * lnw[cb + 32 + lane] + lnb[cb + 32 + lane];
    g_z[basep + lane]      = y0 * (g0r / (1.f + expf(-g0r)));
    g_z[basep + 32 + lane] = y1 * (g1r / (1.f + expf(-g1r)));
}

// ---------------- launch ---------------------------------------------------
extern "C" void kernel_launch(void* const* d_in, const int* in_sizes, int n_in,
                              void* d_out, int out_size) {
    const float* xq     = (const float*)d_in[0];
    const float* tmk    = (const float*)d_in[1];
    const float* tmv    = (const float*)d_in[2];
    const float* tmr    = (const float*)d_in[3];
    const float* tmg    = (const float*)d_in[4];
    const float* tdecay = (const float*)d_in[5];
    const float* tfa    = (const float*)d_in[6];
    const float* Wr     = (const float*)d_in[7];
    const float* Wk     = (const float*)d_in[8];
    const float* Wv     = (const float*)d_in[9];
    const float* Wg     = (const float*)d_in[10];
    const float* Wo     = (const float*)d_in[11];
    const float* lnw    = (const float*)d_in[12];
    const float* lnb    = (const float*)d_in[13];
    float* out = (float*)d_out;

    float *pxr, *pxk, *pxv, *pxg, *pr, *pk, *pv, *pg, *pz;
    cudaGetSymbolAddress((void**)&pxr, g_xr);
    cudaGetSymbolAddress((void**)&pxk, g_xk);
    cudaGetSymbolAddress((void**)&pxv, g_xv);
    cudaGetSymbolAddress((void**)&pxg, g_xg);
    cudaGetSymbolAddress((void**)&pr,  g_r);
    cudaGetSymbolAddress((void**)&pk,  g_k);
    cudaGetSymbolAddress((void**)&pv,  g_v);
    cudaGetSymbolAddress((void**)&pg,  g_g);
    cudaGetSymbolAddress((void**)&pz,  g_z);

    mix_kernel<<<MM * CC / 256, 256>>>(xq, tmk, tmv, tmr, tmg);

    dim3 gg(CC / 128, MM / 128);
    gemm_xwT<<<gg, 256>>>(pxr, Wr, pr, MM, CC, CC);
    gemm_xwT<<<gg, 256>>>(pxk, Wk, pk, MM, CC, CC);
    gemm_xwT<<<gg, 256>>>(pxv, Wv, pv, MM, CC, CC);
    gemm_xwT<<<gg, 256>>>(pxg, Wg, pg, MM, CC, CC);

    state_kernel<<<dim3(BB * HH, 4), 256>>>(tdecay);

    size_t out_smem = OUT_SMEM_FLOATS * sizeof(float);
    cudaFuncSetAttribute(out_kernel,
                         cudaFuncAttributeMaxDynamicSharedMemorySize,
                         (int)out_smem);
    out_kernel<<<BB * HH * NCH, 256, out_smem>>>(tdecay, tfa);

    gn_gate_kernel<<<(MM * HH * 32) / 256, 256>>>(lnw, lnb);

    gemm_xwT<<<gg, 256>>>(pz, Wo, out, MM, CC, CC);
}

// round 4
// speedup vs baseline: 1.6481x; 1.6481x over previous
#include <cuda_runtime.h>
#include <cuda_bf16.h>
#include <stdint.h>
#include <math.h>

// Problem constants
#define BB   4
#define TTT  4096
#define CC   1024
#define HH   16
#define KD   64          // head dim
#define TCH  128         // chunk length
#define NCH  32          // chunks
#define MM   (BB*TTT)    // 16384 rows

// ---------------- scratch (device globals; no allocation allowed) ----------
__device__ __nv_bfloat16 g_xr_h[MM*CC], g_xr_l[MM*CC];
__device__ __nv_bfloat16 g_xk_h[MM*CC], g_xk_l[MM*CC];
__device__ __nv_bfloat16 g_xv_h[MM*CC], g_xv_l[MM*CC];
__device__ __nv_bfloat16 g_xg_h[MM*CC], g_xg_l[MM*CC];
__device__ __nv_bfloat16 g_z_h [MM*CC], g_z_l [MM*CC];
__device__ __nv_bfloat16 g_wr_h[CC*CC], g_wr_l[CC*CC];
__device__ __nv_bfloat16 g_wk_h[CC*CC], g_wk_l[CC*CC];
__device__ __nv_bfloat16 g_wv_h[CC*CC], g_wv_l[CC*CC];
__device__ __nv_bfloat16 g_wg_h[CC*CC], g_wg_l[CC*CC];
__device__ __nv_bfloat16 g_wo_h[CC*CC], g_wo_l[CC*CC];
__device__ float g_r [MM*CC];
__device__ float g_k [MM*CC];
__device__ float g_v [MM*CC];
__device__ float g_g [MM*CC];
__device__ float g_xo[MM*CC];
__device__ float g_states[BB*HH*NCH*KD*KD];

// ---------------- helpers ---------------------------------------------------
__device__ __forceinline__ void split_store(__nv_bfloat16* ah, __nv_bfloat16* al,
                                            size_t i, float v) {
    __nv_bfloat16 h = __float2bfloat16(v);
    ah[i] = h;
    al[i] = __float2bfloat16(v - __bfloat162float(h));
}

__device__ __forceinline__ void mma_bf16(float* c, const uint32_t* a,
                                         uint32_t b0, uint32_t b1) {
    asm volatile(
        "mma.sync.aligned.m16n8k16.row.col.f32.bf16.bf16.f32 "
        "{%0,%1,%2,%3}, {%4,%5,%6,%7}, {%8,%9}, {%0,%1,%2,%3};"
        : "+f"(c[0]), "+f"(c[1]), "+f"(c[2]), "+f"(c[3])
        : "r"(a[0]), "r"(a[1]), "r"(a[2]), "r"(a[3]), "r"(b0), "r"(b1));
}

// ---------------- 0) weight split fp32 -> bf16 hi/lo -----------------------
__global__ void wsplit_kernel(const float* __restrict__ W,
                              __nv_bfloat16* __restrict__ Wh,
                              __nv_bfloat16* __restrict__ Wl) {
    int i = blockIdx.x * blockDim.x + threadIdx.x;
    split_store(Wh, Wl, i, W[i]);
}

// ---------------- 1) time-shift mixing -> bf16 hi/lo ----------------------
__global__ void mix_kernel(const float* __restrict__ x,
                           const float* __restrict__ tmk,
                           const float* __restrict__ tmv,
                           const float* __restrict__ tmr,
                           const float* __restrict__ tmg) {
    int idx = blockIdx.x * blockDim.x + threadIdx.x;   // MM*CC total
    int c = idx & (CC - 1);
    int t = (idx >> 10) & (TTT - 1);
    float xc = x[idx];
    float xp = t ? x[idx - CC] : 0.f;
    float mr = tmr[c]; split_store(g_xr_h, g_xr_l, idx, xc * mr + xp * (1.f - mr));
    float mk = tmk[c]; split_store(g_xk_h, g_xk_l, idx, xc * mk + xp * (1.f - mk));
    float mv = tmv[c]; split_store(g_xv_h, g_xv_l, idx, xc * mv + xp * (1.f - mv));
    float mg = tmg[c]; split_store(g_xg_h, g_xg_l, idx, xc * mg + xp * (1.f - mg));
}

// ---------------- 2) mma.sync GEMM: C = A @ W^T (bf16 hi/lo, 3 passes) -----
// A: MM x CC row-major; W: CC x CC row-major (K contiguous in both).
// CTA tile 128x128, 8 warps (warp tile 32x64), K-chunk 32, double buffer.
#define KCH   32
#define APAD  40                         // padded row stride (elems) -> 80B
#define TS    (128*APAD)                 // one tile in smem (elems)
#define GSM_TOTAL (2*4*TS*2)             // 2 bufs x 4 tiles x TS bf16 = 81920 B
#define NKC   (CC/KCH)                   // 32 chunks

__global__ void __launch_bounds__(256)
gemm_mma(const __nv_bfloat16* __restrict__ Ah, const __nv_bfloat16* __restrict__ Al,
         const __nv_bfloat16* __restrict__ Bh, const __nv_bfloat16* __restrict__ Bl,
         float* __restrict__ C) {
    extern __shared__ __nv_bfloat16 dsm[];
    int tid = threadIdx.x;
    int w   = tid >> 5;
    int lane = tid & 31;
    int g = lane >> 2;           // group id 0..7
    int t = lane & 3;            // thread-in-group
    int n0 = blockIdx.x * 128;
    int m0 = blockIdx.y * 128;
    int m0w = (w >> 1) * 32;     // warp M offset in tile
    int n0w = (w & 1) * 64;      // warp N offset in tile

    const __nv_bfloat16* sAh = Ah + (size_t)m0 * CC;
    const __nv_bfloat16* sAl = Al + (size_t)m0 * CC;
    const __nv_bfloat16* sBh = Bh + (size_t)n0 * CC;
    const __nv_bfloat16* sBl = Bl + (size_t)n0 * CC;

    // per-thread load coords: u = tid + j*256; row=u>>2 (0..127), seg=u&3
    int row0 = tid >> 2,            seg0 = (tid & 3) * 8;
    int row1 = (tid + 256) >> 2,    seg1 = seg0;        // (u&3) same for +256
    size_t go0 = (size_t)row0 * CC + seg0;
    size_t go1 = (size_t)row1 * CC + seg1;
    uint32_t so0 = row0 * APAD + seg0;
    uint32_t so1 = row1 * APAD + seg1;

    float acc[2][8][4];
#pragma unroll
    for (int mi = 0; mi < 2; mi++)
#pragma unroll
        for (int ni = 0; ni < 8; ni++)
#pragma unroll
            for (int q = 0; q < 4; q++) acc[mi][ni][q] = 0.f;

    uint4 pf[8];
    // prologue: chunk 0
    {
        int k0 = 0;
        pf[0] = *(const uint4*)(sAh + go0 + k0); pf[1] = *(const uint4*)(sAh + go1 + k0);
        pf[2] = *(const uint4*)(sAl + go0 + k0); pf[3] = *(const uint4*)(sAl + go1 + k0);
        pf[4] = *(const uint4*)(sBh + go0 + k0); pf[5] = *(const uint4*)(sBh + go1 + k0);
        pf[6] = *(const uint4*)(sBl + go0 + k0); pf[7] = *(const uint4*)(sBl + go1 + k0);
        __nv_bfloat16* b = dsm;   // buf 0
        *(uint4*)(b + 0*TS + so0) = pf[0]; *(uint4*)(b + 0*TS + so1) = pf[1];
        *(uint4*)(b + 1*TS + so0) = pf[2]; *(uint4*)(b + 1*TS + so1) = pf[3];
        *(uint4*)(b + 2*TS + so0) = pf[4]; *(uint4*)(b + 2*TS + so1) = pf[5];
        *(uint4*)(b + 3*TS + so0) = pf[6]; *(uint4*)(b + 3*TS + so1) = pf[7];
        __syncthreads();
    }

    for (int c = 0; c < NKC; ++c) {
        if (c + 1 < NKC) {
            int k0 = (c + 1) * KCH;
            pf[0] = *(const uint4*)(sAh + go0 + k0); pf[1] = *(const uint4*)(sAh + go1 + k0);
            pf[2] = *(const uint4*)(sAl + go0 + k0); pf[3] = *(const uint4*)(sAl + go1 + k0);
            pf[4] = *(const uint4*)(sBh + go0 + k0); pf[5] = *(const uint4*)(sBh + go1 + k0);
            pf[6] = *(const uint4*)(sBl + go0 + k0); pf[7] = *(const uint4*)(sBl + go1 + k0);
        }
        const __nv_bfloat16* sb = dsm + (size_t)(c & 1) * 4 * TS;
        const __nv_bfloat16* tAh = sb;
        const __nv_bfloat16* tAl = sb + TS;
        const __nv_bfloat16* tBh = sb + 2 * TS;
        const __nv_bfloat16* tBl = sb + 3 * TS;
#pragma unroll
        for (int ks = 0; ks < 2; ++ks) {
            int kk = ks * 16;
            uint32_t ah[2][4], al[2][4];
#pragma unroll
            for (int mi = 0; mi < 2; mi++) {
                int rb = m0w + mi * 16;
                ah[mi][0] = *(const uint32_t*)(tAh + (rb + g)     * APAD + kk + 2 * t);
                ah[mi][1] = *(const uint32_t*)(tAh + (rb + g + 8) * APAD + kk + 2 * t);
                ah[mi][2] = *(const uint32_t*)(tAh + (rb + g)     * APAD + kk + 8 + 2 * t);
                ah[mi][3] = *(const uint32_t*)(tAh + (rb + g + 8) * APAD + kk + 8 + 2 * t);
                al[mi][0] = *(const uint32_t*)(tAl + (rb + g)     * APAD + kk + 2 * t);
                al[mi][1] = *(const uint32_t*)(tAl + (rb + g + 8) * APAD + kk + 2 * t);
                al[mi][2] = *(const uint32_t*)(tAl + (rb + g)     * APAD + kk + 8 + 2 * t);
                al[mi][3] = *(const uint32_t*)(tAl + (rb + g + 8) * APAD + kk + 8 + 2 * t);
            }
#pragma unroll
            for (int ni = 0; ni < 8; ni++) {
                int nb = n0w + ni * 8;
                uint32_t bh0 = *(const uint32_t*)(tBh + (nb + g) * APAD + kk + 2 * t);
                uint32_t bh1 = *(const uint32_t*)(tBh + (nb + g) * APAD + kk + 8 + 2 * t);
                uint32_t bl0 = *(const uint32_t*)(tBl + (nb + g) * APAD + kk + 2 * t);
                uint32_t bl1 = *(const uint32_t*)(tBl + (nb + g) * APAD + kk + 8 + 2 * t);
#pragma unroll
                for (int mi = 0; mi < 2; mi++) {
                    mma_bf16(acc[mi][ni], ah[mi], bh0, bh1);
                    mma_bf16(acc[mi][ni], ah[mi], bl0, bl1);
                    mma_bf16(acc[mi][ni], al[mi], bh0, bh1);
                }
            }
        }
        if (c + 1 < NKC) {
            __nv_bfloat16* b = dsm + (size_t)((c + 1) & 1) * 4 * TS;
            *(uint4*)(b + 0*TS + so0) = pf[0]; *(uint4*)(b + 0*TS + so1) = pf[1];
            *(uint4*)(b + 1*TS + so0) = pf[2]; *(uint4*)(b + 1*TS + so1) = pf[3];
            *(uint4*)(b + 2*TS + so0) = pf[4]; *(uint4*)(b + 2*TS + so1) = pf[5];
            *(uint4*)(b + 3*TS + so0) = pf[6]; *(uint4*)(b + 3*TS + so1) = pf[7];
        }
        __syncthreads();
    }

    // epilogue: write fp32
#pragma unroll
    for (int mi = 0; mi < 2; mi++) {
        int r0 = m0 + m0w + mi * 16 + g;
#pragma unroll
        for (int ni = 0; ni < 8; ni++) {
            int col = n0 + n0w + ni * 8 + 2 * t;
            *(float2*)&C[(size_t)r0 * CC + col] =
                make_float2(acc[mi][ni][0], acc[mi][ni][1]);
            *(float2*)&C[(size_t)(r0 + 8) * CC + col] =
                make_float2(acc[mi][ni][2], acc[mi][ni][3]);
        }
    }
}

// ---------------- 3) chunk-boundary states (sequential recurrence) ---------
__global__ void __launch_bounds__(256)
state_kernel(const float* __restrict__ tdecay) {
    __shared__ float kw[TCH * KD];
    __shared__ float vsh[TCH * 16];
    __shared__ float dp[TCH + 1];
    int bh = blockIdx.x;
    int vs = blockIdx.y;
    int b = bh >> 4, h = bh & 15;
    int tid = threadIdx.x;
    float decay = expf(-expf(tdecay[h]));
    if (tid <= TCH) dp[tid] = powf(decay, (float)tid);
    __syncthreads();
    float ws = dp[TCH];
    int tr = tid >> 2;
    int tc = (tid & 3) * 4;
    float s0 = 0.f, s1 = 0.f, s2 = 0.f, s3 = 0.f;
    const float* kb = g_k + ((size_t)b * TTT) * CC + h * KD;
    const float* vb = g_v + ((size_t)b * TTT) * CC + h * KD + vs * 16;
    float* stb = g_states + ((size_t)bh * NCH) * KD * KD;
    for (int n = 0; n < NCH; n++) {
        float* sd = stb + (size_t)n * KD * KD + tr * KD + vs * 16 + tc;
        sd[0] = s0; sd[1] = s1; sd[2] = s2; sd[3] = s3;
        __syncthreads();
        for (int e = tid; e < TCH * KD; e += 256) {
            int j = e >> 6, kk2 = e & 63;
            kw[e] = kb[(size_t)(n * TCH + j) * CC + kk2] * dp[127 - j];
        }
        for (int e = tid; e < TCH * 16; e += 256) {
            int j = e >> 4, cc2 = e & 15;
            vsh[e] = vb[(size_t)(n * TCH + j) * CC + cc2];
        }
        __syncthreads();
        float a0 = 0.f, a1 = 0.f, a2 = 0.f, a3 = 0.f;
#pragma unroll 4
        for (int j = 0; j < TCH; j++) {
            float kv = kw[j * KD + tr];
            float4 v4 = *(const float4*)&vsh[j * 16 + tc];
            a0 = fmaf(kv, v4.x, a0); a1 = fmaf(kv, v4.y, a1);
            a2 = fmaf(kv, v4.z, a2); a3 = fmaf(kv, v4.w, a3);
        }
        s0 = ws * s0 + a0; s1 = ws * s1 + a1;
        s2 = ws * s2 + a2; s3 = ws * s3 + a3;
    }
}

// ---------------- 4) per-chunk attention output (parallel) -----------------
#define OUT_SMEM_FLOATS (TCH*65 + TCH*65 + TCH*KD + KD*KD + TCH*129)
__global__ void __launch_bounds__(256)
out_kernel(const float* __restrict__ tdecay, const float* __restrict__ tfa) {
    extern __shared__ float sm[];
    float* rs  = sm;
    float* ksm = rs  + TCH * 65;
    float* vsm = ksm + TCH * 65;
    float* ssm = vsm + TCH * KD;
    float* att = ssm + KD * KD;
    __shared__ float dp[TCH];
    int bhn = blockIdx.x;
    int n  = bhn & (NCH - 1);
    int bh = bhn >> 5;
    int h = bh & 15, b = bh >> 4;
    int tid = threadIdx.x;
    float decay = expf(-expf(tdecay[h]));
    if (tid < TCH) dp[tid] = powf(decay, (float)tid);
    float u = tfa[h];
    size_t base = ((size_t)(b * TTT + n * TCH)) * CC + h * KD;
    for (int e = tid; e < TCH * KD; e += 256) {
        int i = e >> 6, k2 = e & 63;
        size_t gi = base + (size_t)i * CC + k2;
        rs [i * 65 + k2] = g_r[gi];
        ksm[i * 65 + k2] = g_k[gi];
        vsm[e]           = g_v[gi];
    }
    const float* stp = g_states + ((size_t)bh * NCH + n) * KD * KD;
    for (int e = tid; e < KD * KD; e += 256) ssm[e] = stp[e];
    __syncthreads();
    {
        int i0 = (tid >> 4) * 8, j0 = (tid & 15) * 8;
        float acc[8][8];
#pragma unroll
        for (int i = 0; i < 8; i++)
#pragma unroll
            for (int j = 0; j < 8; j++) acc[i][j] = 0.f;
        for (int k2 = 0; k2 < KD; k2++) {
            float ra[8], rb[8];
#pragma unroll
            for (int ii = 0; ii < 8; ii++) ra[ii] = rs[(i0 + ii) * 65 + k2];
#pragma unroll
            for (int jj = 0; jj < 8; jj++) rb[jj] = ksm[(j0 + jj) * 65 + k2];
#pragma unroll
            for (int ii = 0; ii < 8; ii++)
#pragma unroll
                for (int jj = 0; jj < 8; jj++)
                    acc[ii][jj] = fmaf(ra[ii], rb[jj], acc[ii][jj]);
        }
#pragma unroll
        for (int ii = 0; ii < 8; ii++)
#pragma unroll
            for (int jj = 0; jj < 8; jj++) {
                int i = i0 + ii, j = j0 + jj, d = i - j;
                float w = (d > 0) ? dp[d - 1] : ((d == 0) ? u : 0.f);
                att[i * 129 + j] = acc[ii][jj] * w;
            }
    }
    __syncthreads();
    {
        int i0 = (tid >> 3) * 4, v0 = (tid & 7) * 8;
        float aA[4][8], aB[4][8];
#pragma unroll
        for (int i = 0; i < 4; i++)
#pragma unroll
            for (int j = 0; j < 8; j++) { aA[i][j] = 0.f; aB[i][j] = 0.f; }
        for (int j = 0; j < TCH; j++) {
            float a4[4];
#pragma unroll
            for (int ii = 0; ii < 4; ii++) a4[ii] = att[(i0 + ii) * 129 + j];
            float4 va = *(const float4*)&vsm[j * KD + v0];
            float4 vb2 = *(const float4*)&vsm[j * KD + v0 + 4];
            float vv[8] = {va.x, va.y, va.z, va.w, vb2.x, vb2.y, vb2.z, vb2.w};
#pragma unroll
            for (int ii = 0; ii < 4; ii++)
#pragma unroll
                for (int jj = 0; jj < 8; jj++)
                    aA[ii][jj] = fmaf(a4[ii], vv[jj], aA[ii][jj]);
        }
        for (int k2 = 0; k2 < KD; k2++) {
            float r4[4];
#pragma unroll
            for (int ii = 0; ii < 4; ii++) r4[ii] = rs[(i0 + ii) * 65 + k2];
            float4 sa = *(const float4*)&ssm[k2 * KD + v0];
            float4 sb = *(const float4*)&ssm[k2 * KD + v0 + 4];
            float sv[8] = {sa.x, sa.y, sa.z, sa.w, sb.x, sb.y, sb.z, sb.w};
#pragma unroll
            for (int ii = 0; ii < 4; ii++)
#pragma unroll
                for (int jj = 0; jj < 8; jj++)
                    aB[ii][jj] = fmaf(r4[ii], sv[jj], aB[ii][jj]);
        }
#pragma unroll
        for (int ii = 0; ii < 4; ii++) {
            float wbv = dp[i0 + ii];
#pragma unroll
            for (int jj = 0; jj < 8; jj++)
                g_xo[base + (size_t)(i0 + ii) * CC + v0 + jj] =
                    aA[ii][jj] + wbv * aB[ii][jj];
        }
    }
}

// ---------------- 5) GroupNorm(/8) + silu gate -> bf16 hi/lo ---------------
__global__ void gn_gate_kernel(const float* __restrict__ lnw,
                               const float* __restrict__ lnb) {
    int gidx = blockIdx.x * blockDim.x + threadIdx.x;
    int warp = gidx >> 5, lane = gidx & 31;
    size_t basep = (size_t)warp * 64;
    float a  = g_xo[basep + lane]      * 0.125f;
    float c2 = g_xo[basep + 32 + lane] * 0.125f;
    float s = a + c2, sq = a * a + c2 * c2;
#pragma unroll
    for (int o = 16; o; o >>= 1) {
        s  += __shfl_xor_sync(0xffffffffu, s,  o);
        sq += __shfl_xor_sync(0xffffffffu, sq, o);
    }
    float mu  = s * (1.f / 64.f);
    float var = sq * (1.f / 64.f) - mu * mu;
    float inv = rsqrtf(var + 1e-5f);
    int h = warp & 15;
    int cb = h * 64;
    float g0r = g_g[basep + lane];
    float g1r = g_g[basep + 32 + lane];
    float y0 = ((a  - mu) * inv) * lnw[cb + lane]      + lnb[cb + lane];
    float y1 = ((c2 - mu) * inv) * lnw[cb + 32 + lane] + lnb[cb + 32 + lane];
    split_store(g_z_h, g_z_l, basep + lane,      y0 * (g0r / (1.f + expf(-g0r))));
    split_store(g_z_h, g_z_l, basep + 32 + lane, y1 * (g1r / (1.f + expf(-g1r))));
}

// ---------------- launch ---------------------------------------------------
extern "C" void kernel_launch(void* const* d_in, const int* in_sizes, int n_in,
                              void* d_out, int out_size) {
    const float* xq     = (const float*)d_in[0];
    const float* tmk    = (const float*)d_in[1];
    const float* tmv    = (const float*)d_in[2];
    const float* tmr    = (const float*)d_in[3];
    const float* tmg    = (const float*)d_in[4];
    const float* tdecay = (const float*)d_in[5];
    const float* tfa    = (const float*)d_in[6];
    const float* Wr     = (const float*)d_in[7];
    const float* Wk     = (const float*)d_in[8];
    const float* Wv     = (const float*)d_in[9];
    const float* Wg     = (const float*)d_in[10];
    const float* Wo     = (const float*)d_in[11];
    const float* lnw    = (const float*)d_in[12];
    const float* lnb    = (const float*)d_in[13];
    float* out = (float*)d_out;

    __nv_bfloat16 *pxr_h, *pxr_l, *pxk_h, *pxk_l, *pxv_h, *pxv_l, *pxg_h, *pxg_l;
    __nv_bfloat16 *pz_h, *pz_l;
    __nv_bfloat16 *pwr_h, *pwr_l, *pwk_h, *pwk_l, *pwv_h, *pwv_l, *pwg_h, *pwg_l,
                  *pwo_h, *pwo_l;
    float *pr, *pk, *pv, *pg;
    cudaGetSymbolAddress((void**)&pxr_h, g_xr_h); cudaGetSymbolAddress((void**)&pxr_l, g_xr_l);
    cudaGetSymbolAddress((void**)&pxk_h, g_xk_h); cudaGetSymbolAddress((void**)&pxk_l, g_xk_l);
    cudaGetSymbolAddress((void**)&pxv_h, g_xv_h); cudaGetSymbolAddress((void**)&pxv_l, g_xv_l);
    cudaGetSymbolAddress((void**)&pxg_h, g_xg_h); cudaGetSymbolAddress((void**)&pxg_l, g_xg_l);
    cudaGetSymbolAddress((void**)&pz_h,  g_z_h);  cudaGetSymbolAddress((void**)&pz_l,  g_z_l);
    cudaGetSymbolAddress((void**)&pwr_h, g_wr_h); cudaGetSymbolAddress((void**)&pwr_l, g_wr_l);
    cudaGetSymbolAddress((void**)&pwk_h, g_wk_h); cudaGetSymbolAddress((void**)&pwk_l, g_wk_l);
    cudaGetSymbolAddress((void**)&pwv_h, g_wv_h); cudaGetSymbolAddress((void**)&pwv_l, g_wv_l);
    cudaGetSymbolAddress((void**)&pwg_h, g_wg_h); cudaGetSymbolAddress((void**)&pwg_l, g_wg_l);
    cudaGetSymbolAddress((void**)&pwo_h, g_wo_h); cudaGetSymbolAddress((void**)&pwo_l, g_wo_l);
    cudaGetSymbolAddress((void**)&pr, g_r); cudaGetSymbolAddress((void**)&pk, g_k);
    cudaGetSymbolAddress((void**)&pv, g_v); cudaGetSymbolAddress((void**)&pg, g_g);

    int wgrid = CC * CC / 256;
    wsplit_kernel<<<wgrid, 256>>>(Wr, pwr_h, pwr_l);
    wsplit_kernel<<<wgrid, 256>>>(Wk, pwk_h, pwk_l);
    wsplit_kernel<<<wgrid, 256>>>(Wv, pwv_h, pwv_l);
    wsplit_kernel<<<wgrid, 256>>>(Wg, pwg_h, pwg_l);
    wsplit_kernel<<<wgrid, 256>>>(Wo, pwo_h, pwo_l);

    mix_kernel<<<MM * CC / 256, 256>>>(xq, tmk, tmv, tmr, tmg);

    cudaFuncSetAttribute(gemm_mma, cudaFuncAttributeMaxDynamicSharedMemorySize,
                         GSM_TOTAL);
    dim3 gg(CC / 128, MM / 128);
    gemm_mma<<<gg, 256, GSM_TOTAL>>>(pxr_h, pxr_l, pwr_h, pwr_l, pr);
    gemm_mma<<<gg, 256, GSM_TOTAL>>>(pxk_h, pxk_l, pwk_h, pwk_l, pk);
    gemm_mma<<<gg, 256, GSM_TOTAL>>>(pxv_h, pxv_l, pwv_h, pwv_l, pv);
    gemm_mma<<<gg, 256, GSM_TOTAL>>>(pxg_h, pxg_l, pwg_h, pwg_l, pg);

    state_kernel<<<dim3(BB * HH, 4), 256>>>(tdecay);

    size_t out_smem = OUT_SMEM_FLOATS * sizeof(float);
    cudaFuncSetAttribute(out_kernel, cudaFuncAttributeMaxDynamicSharedMemorySize,
                         (int)out_smem);
    out_kernel<<<BB * HH * NCH, 256, out_smem>>>(tdecay, tfa);

    gn_gate_kernel<<<(MM * HH * 32) / 256, 256>>>(lnw, lnb);

    gemm_mma<<<gg, 256, GSM_TOTAL>>>(pz_h, pz_l, pwo_h, pwo_l, out);
}